// round 1
// baseline (speedup 1.0000x reference)
#include <cuda_runtime.h>
#include <math.h>

// ---------------------------------------------------------------------------
// Problem constants
// ---------------------------------------------------------------------------
constexpr int NTOK = 2048;          // tokens
constexpr int DM   = 2048;          // model dim
constexpr int NH_  = 16;            // q heads
constexpr int NKV_ = 4;             // kv heads
constexpr int HD_  = 128;           // head dim
constexpr int NE_  = 4;             // experts
constexpr int EI_  = 2048;          // expert intermediate (I/E)
constexpr int CHK  = NTOK / NE_;    // 512 tokens per expert
constexpr float REPS = 1e-6f;

// ---------------------------------------------------------------------------
// Scratch (device globals — no runtime allocation allowed)
// ---------------------------------------------------------------------------
__device__ float g_hnorm[(size_t)NTOK * DM];
__device__ float g_q   [(size_t)NTOK * DM];
__device__ float g_k   [(size_t)NTOK * NKV_ * HD_];
__device__ float g_v   [(size_t)NTOK * NKV_ * HD_];
__device__ float g_attn[(size_t)NTOK * DM];
__device__ float g_h1  [(size_t)NTOK * DM];
__device__ float g_hn2 [(size_t)NTOK * DM];
__device__ float g_gu  [(size_t)NTOK * 2 * EI_];
__device__ float g_act [(size_t)NTOK * EI_];
__device__ float g_tmp [(size_t)NTOK * DM];      // o_out, then mlp_out
__device__ int   g_pos [NTOK];
__device__ int   g_sidx[NTOK];

// ---------------------------------------------------------------------------
// Index prep: detect int32 vs int64 (jnp.int64 silently downcasts to int32
// when x64 is disabled). positions = arange(N): int64 view as int32 words is
// [0,0,1,0,...] -> w[1]==0 && w[2]==1; int32 is [0,1,2,...] -> w[1]==1.
// ---------------------------------------------------------------------------
__global__ void prep_idx_kernel(const void* pos, const void* sidx)
{
    int i = blockIdx.x * blockDim.x + threadIdx.x;
    if (i >= NTOK) return;
    const int* w = (const int*)pos;
    bool is64 = (w[1] == 0 && w[2] == 1);
    if (is64) {
        g_pos[i]  = (int)((const long long*)pos)[i];
        g_sidx[i] = (int)((const long long*)sidx)[i];
    } else {
        g_pos[i]  = w[i];
        g_sidx[i] = ((const int*)sidx)[i];
    }
}

// ---------------------------------------------------------------------------
// Row RMSNorm: one block (256 thr) per row of D=2048
// ---------------------------------------------------------------------------
__global__ void rmsnorm_kernel(const float* __restrict__ x,
                               const float* __restrict__ w,
                               float* __restrict__ out)
{
    int row = blockIdx.x;
    const float* xr = x + (size_t)row * DM;
    float ss = 0.f;
    for (int j = threadIdx.x; j < DM; j += 256) { float v = xr[j]; ss += v * v; }
    #pragma unroll
    for (int o = 16; o > 0; o >>= 1) ss += __shfl_xor_sync(0xffffffffu, ss, o);
    __shared__ float wsum[8];
    if ((threadIdx.x & 31) == 0) wsum[threadIdx.x >> 5] = ss;
    __syncthreads();
    float tot = 0.f;
    #pragma unroll
    for (int i = 0; i < 8; ++i) tot += wsum[i];
    float rs = rsqrtf(tot / (float)DM + REPS);
    float* orow = out + (size_t)row * DM;
    for (int j = threadIdx.x; j < DM; j += 256) orow[j] = xr[j] * rs * w[j];
}

// ---------------------------------------------------------------------------
// SGEMM NN (C = A * B), 128x128x16 tiles, 8x8 microtile, 256 threads.
// Optional row gather on A and row scatter on C via g_sidx (routed experts).
// blockIdx.z selects expert (weight offset e*wStride, rows e*rowsPerE..).
// ---------------------------------------------------------------------------
__global__ __launch_bounds__(256, 2)
void sgemm_nn_kernel(const float* __restrict__ A, const float* __restrict__ B,
                     float* __restrict__ C, int K, int Nc,
                     int rowsPerE, size_t wStride, int gatherF, int scatterF)
{
    __shared__ float As[16][128];
    __shared__ float Bs[16][128];
    const int t    = threadIdx.x;
    const int e    = blockIdx.z;
    const int row0 = e * rowsPerE + blockIdx.y * 128;
    const int n0   = blockIdx.x * 128;
    const float* Bp = B + (size_t)e * wStride;
    const int tx = t & 15, ty = t >> 4;

    int ar_[2], ak_[2]; size_t aoff_[2];
    #pragma unroll
    for (int it = 0; it < 2; ++it) {
        int fid = t + it * 256;
        int r = fid >> 2, kq = fid & 3;
        int gr = row0 + r;
        int arow = gatherF ? g_sidx[gr] : gr;
        ar_[it] = r; ak_[it] = kq;
        aoff_[it] = (size_t)arow * K + kq * 4;
    }

    float acc[8][8];
    #pragma unroll
    for (int i = 0; i < 8; ++i)
        #pragma unroll
        for (int j = 0; j < 8; ++j) acc[i][j] = 0.f;

    for (int kt = 0; kt < K; kt += 16) {
        #pragma unroll
        for (int it = 0; it < 2; ++it) {
            float4 va = *(const float4*)(A + aoff_[it] + kt);
            As[ak_[it]*4 + 0][ar_[it]] = va.x;
            As[ak_[it]*4 + 1][ar_[it]] = va.y;
            As[ak_[it]*4 + 2][ar_[it]] = va.z;
            As[ak_[it]*4 + 3][ar_[it]] = va.w;
        }
        #pragma unroll
        for (int it = 0; it < 2; ++it) {
            int fid = t + it * 256;
            int kr = fid >> 5, nq = fid & 31;
            *(float4*)&Bs[kr][nq*4] =
                *(const float4*)(Bp + (size_t)(kt + kr) * Nc + n0 + nq * 4);
        }
        __syncthreads();
        #pragma unroll
        for (int kk = 0; kk < 16; ++kk) {
            float a[8], b[8];
            *(float4*)(a)     = *(const float4*)&As[kk][ty*8];
            *(float4*)(a + 4) = *(const float4*)&As[kk][ty*8 + 4];
            *(float4*)(b)     = *(const float4*)&Bs[kk][tx*8];
            *(float4*)(b + 4) = *(const float4*)&Bs[kk][tx*8 + 4];
            #pragma unroll
            for (int i = 0; i < 8; ++i)
                #pragma unroll
                for (int j = 0; j < 8; ++j)
                    acc[i][j] = fmaf(a[i], b[j], acc[i][j]);
        }
        __syncthreads();
    }

    #pragma unroll
    for (int i = 0; i < 8; ++i) {
        int gr = row0 + ty*8 + i;
        int cr = scatterF ? g_sidx[gr] : gr;
        float* cp = C + (size_t)cr * Nc + n0 + tx*8;
        *(float4*)(cp)     = make_float4(acc[i][0], acc[i][1], acc[i][2], acc[i][3]);
        *(float4*)(cp + 4) = make_float4(acc[i][4], acc[i][5], acc[i][6], acc[i][7]);
    }
}

// ---------------------------------------------------------------------------
// SGEMM NT (C = A * B^T), B row-major (Nc x K). blockIdx.z selects (B0,C0) or
// (B1,C1) so k & v share one launch. Optional bias epilogue: + clip(bias,0,2)
// (used by mu_current).
// ---------------------------------------------------------------------------
__global__ __launch_bounds__(256, 2)
void sgemm_nt_kernel(const float* __restrict__ A,
                     const float* __restrict__ B0, const float* __restrict__ B1,
                     float* __restrict__ C0, float* __restrict__ C1,
                     int K, int Nc, const float* __restrict__ bias)
{
    __shared__ float As[16][128];
    __shared__ float Bs[16][128];
    const int t = threadIdx.x;
    const float* B = blockIdx.z ? B1 : B0;
    float* C       = blockIdx.z ? C1 : C0;
    const int row0 = blockIdx.y * 128;
    const int n0   = blockIdx.x * 128;
    const int tx = t & 15, ty = t >> 4;

    float acc[8][8];
    #pragma unroll
    for (int i = 0; i < 8; ++i)
        #pragma unroll
        for (int j = 0; j < 8; ++j) acc[i][j] = 0.f;

    for (int kt = 0; kt < K; kt += 16) {
        #pragma unroll
        for (int it = 0; it < 2; ++it) {
            int fid = t + it * 256;
            int r = fid >> 2, kq = fid & 3;
            float4 va = *(const float4*)(A + (size_t)(row0 + r) * K + kt + kq * 4);
            As[kq*4 + 0][r] = va.x;
            As[kq*4 + 1][r] = va.y;
            As[kq*4 + 2][r] = va.z;
            As[kq*4 + 3][r] = va.w;
            float4 vb = *(const float4*)(B + (size_t)(n0 + r) * K + kt + kq * 4);
            Bs[kq*4 + 0][r] = vb.x;
            Bs[kq*4 + 1][r] = vb.y;
            Bs[kq*4 + 2][r] = vb.z;
            Bs[kq*4 + 3][r] = vb.w;
        }
        __syncthreads();
        #pragma unroll
        for (int kk = 0; kk < 16; ++kk) {
            float a[8], b[8];
            *(float4*)(a)     = *(const float4*)&As[kk][ty*8];
            *(float4*)(a + 4) = *(const float4*)&As[kk][ty*8 + 4];
            *(float4*)(b)     = *(const float4*)&Bs[kk][tx*8];
            *(float4*)(b + 4) = *(const float4*)&Bs[kk][tx*8 + 4];
            #pragma unroll
            for (int i = 0; i < 8; ++i)
                #pragma unroll
                for (int j = 0; j < 8; ++j)
                    acc[i][j] = fmaf(a[i], b[j], acc[i][j]);
        }
        __syncthreads();
    }

    float bb[8];
    #pragma unroll
    for (int j = 0; j < 8; ++j) bb[j] = 0.f;
    if (bias) {
        #pragma unroll
        for (int j = 0; j < 8; ++j)
            bb[j] = fminf(fmaxf(bias[n0 + tx*8 + j], 0.f), 2.f);
    }
    #pragma unroll
    for (int i = 0; i < 8; ++i) {
        int cr = row0 + ty*8 + i;
        float* cp = C + (size_t)cr * Nc + n0 + tx*8;
        *(float4*)(cp)     = make_float4(acc[i][0]+bb[0], acc[i][1]+bb[1],
                                         acc[i][2]+bb[2], acc[i][3]+bb[3]);
        *(float4*)(cp + 4) = make_float4(acc[i][4]+bb[4], acc[i][5]+bb[5],
                                         acc[i][6]+bb[6], acc[i][7]+bb[7]);
    }
}

// ---------------------------------------------------------------------------
// Fused per-(token,head) RMSNorm + RoPE. One block of 128 threads per head.
// In-place on q / k buffers.
// ---------------------------------------------------------------------------
__global__ void qknorm_rope_kernel(float* __restrict__ x,
                                   const float* __restrict__ w, int nheads)
{
    int n = blockIdx.x / nheads;
    int h = blockIdx.x % nheads;
    int d = threadIdx.x;
    float* xr = x + ((size_t)n * nheads + h) * HD_;
    float v = xr[d];
    float ss = v * v;
    #pragma unroll
    for (int o = 16; o > 0; o >>= 1) ss += __shfl_xor_sync(0xffffffffu, ss, o);
    __shared__ float ws[4];
    if ((d & 31) == 0) ws[d >> 5] = ss;
    __syncthreads();
    float tot = ws[0] + ws[1] + ws[2] + ws[3];
    float rs = rsqrtf(tot / (float)HD_ + REPS);
    __shared__ float s[HD_];
    s[d] = v * rs * w[d];
    __syncthreads();
    float pos = (float)g_pos[n];
    int fi = d & 63;
    float invf = 1.0f / (float)pow(10000.0, (double)fi / 64.0);
    float ang = pos * invf;
    float c, sn;
    sincosf(ang, &sn, &c);
    float o = (d < 64) ? (s[d] * c - s[d + 64] * sn)
                       : (s[d] * c + s[d - 64] * sn);
    xr[d] = o;
}

// ---------------------------------------------------------------------------
// Causal GQA flash attention, fp32. Block = (64 q rows, 1 head), 128 threads.
// Online softmax with 64-wide KV tiles, everything staged in shared memory.
// ---------------------------------------------------------------------------
constexpr int ATTN_SMEM = (3 * 64 * 128 + 64 * 68 + 3 * 64) * 4;  // 116480 B

__global__ __launch_bounds__(128)
void attn_kernel()
{
    extern __shared__ float sm[];
    float* Qs  = sm;                      // 64 x 128
    float* Ks  = Qs + 64 * 128;           // 64 x 128
    float* Vs  = Ks + 64 * 128;           // 64 x 128
    float* S   = Vs + 64 * 128;           // 64 x 68 (padded)
    float* m_s = S + 64 * 68;
    float* l_s = m_s + 64;
    float* al_s = l_s + 64;

    const int t    = threadIdx.x;
    const int qt   = blockIdx.x;
    const int head = blockIdx.y;
    const int kvh  = head >> 2;           // NH/NKV = 4
    const int q0   = qt * 64;
    const float scale = 0.08838834764831845f;   // 1/sqrt(128)

    #pragma unroll
    for (int it = 0; it < 16; ++it) {
        int fid = t + it * 128;
        int r = fid >> 5, cq = fid & 31;
        *(float4*)&Qs[r*128 + cq*4] =
            *(const float4*)(g_q + (size_t)(q0 + r) * (NH_*HD_) + head * HD_ + cq * 4);
    }
    if (t < 64) { m_s[t] = -1e30f; l_s[t] = 0.f; }

    float acc[4][16];
    #pragma unroll
    for (int i = 0; i < 4; ++i)
        #pragma unroll
        for (int c = 0; c < 16; ++c) acc[i][c] = 0.f;

    const int rg = t >> 3, cg = t & 7;

    for (int kt = 0; kt <= qt; ++kt) {
        const int k0 = kt * 64;
        __syncthreads();
        #pragma unroll
        for (int it = 0; it < 16; ++it) {
            int fid = t + it * 128;
            int r = fid >> 5, cq = fid & 31;
            *(float4*)&Ks[r*128 + cq*4] =
                *(const float4*)(g_k + (size_t)(k0 + r) * (NKV_*HD_) + kvh * HD_ + cq * 4);
            *(float4*)&Vs[r*128 + cq*4] =
                *(const float4*)(g_v + (size_t)(k0 + r) * (NKV_*HD_) + kvh * HD_ + cq * 4);
        }
        __syncthreads();

        // S = Q K^T : thread computes 4x8 microtile
        float s[4][8];
        #pragma unroll
        for (int i = 0; i < 4; ++i)
            #pragma unroll
            for (int j = 0; j < 8; ++j) s[i][j] = 0.f;
        #pragma unroll 4
        for (int d = 0; d < 128; ++d) {
            float a0 = Qs[(rg*4 + 0)*128 + d];
            float a1 = Qs[(rg*4 + 1)*128 + d];
            float a2 = Qs[(rg*4 + 2)*128 + d];
            float a3 = Qs[(rg*4 + 3)*128 + d];
            #pragma unroll
            for (int j = 0; j < 8; ++j) {
                float b = Ks[(cg*8 + j)*128 + d];
                s[0][j] = fmaf(a0, b, s[0][j]);
                s[1][j] = fmaf(a1, b, s[1][j]);
                s[2][j] = fmaf(a2, b, s[2][j]);
                s[3][j] = fmaf(a3, b, s[3][j]);
            }
        }
        const bool diag = (kt == qt);
        #pragma unroll
        for (int i = 0; i < 4; ++i) {
            int qr = q0 + rg*4 + i;
            #pragma unroll
            for (int j = 0; j < 8; ++j) {
                int kc = k0 + cg*8 + j;
                float v = s[i][j] * scale;
                if (diag && kc > qr) v = -1e9f;
                S[(rg*4 + i)*68 + cg*8 + j] = v;
            }
        }
        __syncthreads();

        // online softmax: one thread per row
        if (t < 64) {
            float mold = m_s[t];
            float mx = mold;
            #pragma unroll 8
            for (int j = 0; j < 64; ++j) mx = fmaxf(mx, S[t*68 + j]);
            float sum = 0.f;
            #pragma unroll 8
            for (int j = 0; j < 64; ++j) {
                float p = __expf(S[t*68 + j] - mx);
                S[t*68 + j] = p;
                sum += p;
            }
            float al = __expf(mold - mx);
            m_s[t] = mx;
            l_s[t] = l_s[t] * al + sum;
            al_s[t] = al;
        }
        __syncthreads();

        // O = O*alpha + P V : thread owns 4 rows x 16 cols
        #pragma unroll
        for (int i = 0; i < 4; ++i) {
            float al = al_s[rg*4 + i];
            #pragma unroll
            for (int c = 0; c < 16; ++c) acc[i][c] *= al;
        }
        #pragma unroll 2
        for (int j = 0; j < 64; ++j) {
            float p0 = S[(rg*4 + 0)*68 + j];
            float p1 = S[(rg*4 + 1)*68 + j];
            float p2 = S[(rg*4 + 2)*68 + j];
            float p3 = S[(rg*4 + 3)*68 + j];
            float vv[16];
            *(float4*)(vv)      = *(const float4*)&Vs[j*128 + cg*16 + 0];
            *(float4*)(vv + 4)  = *(const float4*)&Vs[j*128 + cg*16 + 4];
            *(float4*)(vv + 8)  = *(const float4*)&Vs[j*128 + cg*16 + 8];
            *(float4*)(vv + 12) = *(const float4*)&Vs[j*128 + cg*16 + 12];
            #pragma unroll
            for (int c = 0; c < 16; ++c) {
                acc[0][c] = fmaf(p0, vv[c], acc[0][c]);
                acc[1][c] = fmaf(p1, vv[c], acc[1][c]);
                acc[2][c] = fmaf(p2, vv[c], acc[2][c]);
                acc[3][c] = fmaf(p3, vv[c], acc[3][c]);
            }
        }
    }

    #pragma unroll
    for (int i = 0; i < 4; ++i) {
        int r = rg*4 + i;
        float inv = 1.f / l_s[r];
        float* op = g_attn + (size_t)(q0 + r) * (NH_*HD_) + head * HD_ + cg * 16;
        #pragma unroll
        for (int c = 0; c < 16; ++c) op[c] = acc[i][c] * inv;
    }
}

// ---------------------------------------------------------------------------
// SiLU(gate) * up on the sorted gate_up output
// ---------------------------------------------------------------------------
__global__ void silu_kernel()
{
    int i = blockIdx.x * 256 + threadIdx.x;
    if (i >= NTOK * EI_) return;
    int r = i / EI_, c = i % EI_;
    float gt = g_gu[(size_t)r * (2*EI_) + c];
    float up = g_gu[(size_t)r * (2*EI_) + EI_ + c];
    g_act[i] = gt / (1.f + __expf(-gt)) * up;
}

__global__ void add_kernel(const float* __restrict__ a,
                           const float* __restrict__ b,
                           float* __restrict__ c, int n)
{
    int i = blockIdx.x * 256 + threadIdx.x;
    if (i < n) c[i] = a[i] + b[i];
}

// ---------------------------------------------------------------------------
// Launcher
// ---------------------------------------------------------------------------
extern "C" void kernel_launch(void* const* d_in, const int* in_sizes, int n_in,
                              void* d_out, int out_size)
{
    const float* hidden     = (const float*)d_in[0];
    const void*  positions  = d_in[1];
    const void*  sortidx    = d_in[2];
    const float* input_ln_w = (const float*)d_in[3];
    const float* q_proj_w   = (const float*)d_in[4];
    const float* o_proj_w   = (const float*)d_in[5];
    const float* k_w        = (const float*)d_in[6];
    const float* v_w        = (const float*)d_in[7];
    const float* q_norm_w   = (const float*)d_in[8];
    const float* k_norm_w   = (const float*)d_in[9];
    const float* mu         = (const float*)d_in[10];
    const float* mu_proj_w  = (const float*)d_in[11];
    const float* post_ln_w  = (const float*)d_in[12];
    const float* gate_up_w  = (const float*)d_in[13];
    const float* down_w     = (const float*)d_in[14];

    float* out_h  = (float*)d_out;
    float* out_mu = out_h + (size_t)NTOK * DM;

    float *p_hnorm, *p_q, *p_k, *p_v, *p_attn, *p_h1, *p_hn2, *p_gu, *p_act, *p_tmp;
    cudaGetSymbolAddress((void**)&p_hnorm, g_hnorm);
    cudaGetSymbolAddress((void**)&p_q,     g_q);
    cudaGetSymbolAddress((void**)&p_k,     g_k);
    cudaGetSymbolAddress((void**)&p_v,     g_v);
    cudaGetSymbolAddress((void**)&p_attn,  g_attn);
    cudaGetSymbolAddress((void**)&p_h1,    g_h1);
    cudaGetSymbolAddress((void**)&p_hn2,   g_hn2);
    cudaGetSymbolAddress((void**)&p_gu,    g_gu);
    cudaGetSymbolAddress((void**)&p_act,   g_act);
    cudaGetSymbolAddress((void**)&p_tmp,   g_tmp);

    cudaFuncSetAttribute(attn_kernel,
                         cudaFuncAttributeMaxDynamicSharedMemorySize, ATTN_SMEM);

    // 1) normalize index dtype
    prep_idx_kernel<<<(NTOK + 255) / 256, 256>>>(positions, sortidx);

    // 2) input RMSNorm
    rmsnorm_kernel<<<NTOK, 256>>>(hidden, input_ln_w, p_hnorm);

    // 3) q = routed_proj(hnorm, q_proj_w)  [gather+scatter]
    sgemm_nn_kernel<<<dim3(16, 4, 4), 256>>>(p_hnorm, q_proj_w, p_q,
                                             DM, NH_*HD_, CHK,
                                             (size_t)DM * (NH_*HD_), 1, 1);

    // 4) k, v = hnorm @ {k_w, v_w}^T (fused in one launch via blockIdx.z)
    sgemm_nt_kernel<<<dim3(4, 16, 2), 256>>>(p_hnorm, k_w, v_w, p_k, p_v,
                                             DM, NKV_*HD_, nullptr);

    // 5) per-head RMSNorm + RoPE (in place)
    qknorm_rope_kernel<<<NTOK * NH_,  HD_>>>(p_q, q_norm_w, NH_);
    qknorm_rope_kernel<<<NTOK * NKV_, HD_>>>(p_k, k_norm_w, NKV_);

    // 6) causal GQA attention
    attn_kernel<<<dim3(NTOK / 64, NH_), 128, ATTN_SMEM>>>();

    // 7) o = routed_proj(attn, o_proj_w)  [gather+scatter]
    sgemm_nn_kernel<<<dim3(16, 4, 4), 256>>>(p_attn, o_proj_w, p_tmp,
                                             NH_*HD_, DM, CHK,
                                             (size_t)(NH_*HD_) * DM, 1, 1);

    // 8) h1 = residual + o
    add_kernel<<<(NTOK*DM + 255) / 256, 256>>>(hidden, p_tmp, p_h1, NTOK*DM);

    // 9) mu_current = clip(mu,0,2) + h1 @ mu_proj_w^T  -> second half of d_out
    sgemm_nt_kernel<<<dim3(16, 16, 1), 256>>>(p_h1, mu_proj_w, mu_proj_w,
                                              out_mu, out_mu, DM, DM, mu);

    // 10) post RMSNorm
    rmsnorm_kernel<<<NTOK, 256>>>(p_h1, post_ln_w, p_hn2);

    // 11) gate_up (sorted output, gather only)
    sgemm_nn_kernel<<<dim3(32, 4, 4), 256>>>(p_hn2, gate_up_w, p_gu,
                                             DM, 2*EI_, CHK,
                                             (size_t)DM * 2 * EI_, 1, 0);

    // 12) act = silu(gate) * up  (sorted order)
    silu_kernel<<<(NTOK*EI_ + 255) / 256, 256>>>();

    // 13) down proj (scatter back)
    sgemm_nn_kernel<<<dim3(16, 4, 4), 256>>>(p_act, down_w, p_tmp,
                                             EI_, DM, CHK,
                                             (size_t)EI_ * DM, 0, 1);

    // 14) h = h1 + mlp_out -> first half of d_out
    add_kernel<<<(NTOK*DM + 255) / 256, 256>>>(p_h1, p_tmp, out_h, NTOK*DM);
}

// round 2
// speedup vs baseline: 1.2433x; 1.2433x over previous
#include <cuda_runtime.h>
#include <cuda_bf16.h>
#include <math.h>

// ---------------------------------------------------------------------------
// Problem constants
// ---------------------------------------------------------------------------
constexpr int NTOK = 2048;
constexpr int DM   = 2048;
constexpr int NH_  = 16;
constexpr int NKV_ = 4;
constexpr int HD_  = 128;
constexpr int EI_  = 2048;
constexpr int CHK  = NTOK / 4;      // 512 tokens per expert
constexpr float REPS = 1e-6f;

// ---------------------------------------------------------------------------
// Scratch
// ---------------------------------------------------------------------------
__device__ float g_hnorm[(size_t)NTOK * DM];
__device__ float g_q   [(size_t)NTOK * DM];
__device__ float g_k   [(size_t)NTOK * NKV_ * HD_];
__device__ float g_v   [(size_t)NTOK * NKV_ * HD_];
__device__ float g_attn[(size_t)NTOK * DM];
__device__ float g_h1  [(size_t)NTOK * DM];
__device__ float g_hn2 [(size_t)NTOK * DM];
__device__ float g_gu  [(size_t)NTOK * 2 * EI_];
__device__ float g_act [(size_t)NTOK * EI_];
__device__ int   g_pos [NTOK];
__device__ int   g_sidx[NTOK];

// ---------------------------------------------------------------------------
// Index prep (int64-vs-int32 autodetect; positions = arange)
// ---------------------------------------------------------------------------
__global__ void prep_idx_kernel(const void* pos, const void* sidx)
{
    int i = blockIdx.x * blockDim.x + threadIdx.x;
    if (i >= NTOK) return;
    const int* w = (const int*)pos;
    bool is64 = (w[1] == 0 && w[2] == 1);
    if (is64) {
        g_pos[i]  = (int)((const long long*)pos)[i];
        g_sidx[i] = (int)((const long long*)sidx)[i];
    } else {
        g_pos[i]  = w[i];
        g_sidx[i] = ((const int*)sidx)[i];
    }
}

// ---------------------------------------------------------------------------
// Row RMSNorm
// ---------------------------------------------------------------------------
__global__ void rmsnorm_kernel(const float* __restrict__ x,
                               const float* __restrict__ w,
                               float* __restrict__ out)
{
    int row = blockIdx.x;
    const float* xr = x + (size_t)row * DM;
    float ss = 0.f;
    for (int j = threadIdx.x; j < DM; j += 256) { float v = xr[j]; ss += v * v; }
    #pragma unroll
    for (int o = 16; o > 0; o >>= 1) ss += __shfl_xor_sync(0xffffffffu, ss, o);
    __shared__ float wsum[8];
    if ((threadIdx.x & 31) == 0) wsum[threadIdx.x >> 5] = ss;
    __syncthreads();
    float tot = 0.f;
    #pragma unroll
    for (int i = 0; i < 8; ++i) tot += wsum[i];
    float rs = rsqrtf(tot / (float)DM + REPS);
    float* orow = out + (size_t)row * DM;
    for (int j = threadIdx.x; j < DM; j += 256) orow[j] = xr[j] * rs * w[j];
}

// ---------------------------------------------------------------------------
// Split-bf16 helpers: x = hi + lo, both bf16 -> ~fp32-accurate GEMM via
// Ah*Bh + Ah*Bl + Al*Bh with fp32 HMMA accumulation.
// ---------------------------------------------------------------------------
__device__ __forceinline__ unsigned pack_bf(float x, float y)
{
    unsigned short ux = __bfloat16_as_ushort(__float2bfloat16_rn(x));
    unsigned short uy = __bfloat16_as_ushort(__float2bfloat16_rn(y));
    return (unsigned)ux | ((unsigned)uy << 16);
}
__device__ __forceinline__ void split_pack(float x, float y,
                                           unsigned& hi, unsigned& lo)
{
    __nv_bfloat16 bx = __float2bfloat16_rn(x);
    __nv_bfloat16 by = __float2bfloat16_rn(y);
    hi = (unsigned)__bfloat16_as_ushort(bx) |
         ((unsigned)__bfloat16_as_ushort(by) << 16);
    lo = pack_bf(x - __bfloat162float(bx), y - __bfloat162float(by));
}

#define MMA_BF16(d, a0, a1, a2, a3, b0, b1)                                   \
    asm volatile("mma.sync.aligned.m16n8k16.row.col.f32.bf16.bf16.f32 "       \
                 "{%0,%1,%2,%3}, {%4,%5,%6,%7}, {%8,%9}, {%0,%1,%2,%3};"      \
                 : "+f"(d[0]), "+f"(d[1]), "+f"(d[2]), "+f"(d[3])             \
                 : "r"(a0), "r"(a1), "r"(a2), "r"(a3), "r"(b0), "r"(b1))

// ---------------------------------------------------------------------------
// Tensor-core GEMM: C[M,Nc] = A[M,K] * W  (+bias clip / +residual)
//   transB=0: W is [K,Nc] row-major (NN).  transB=1: W is [Nc,K] (NT).
// Tiles 128x128x32, 256 threads = 8 warps (2m x 4n), warp tile 64x32.
// SMEM word layout [row][k2] (k2 = k/2 pair packed bf16x2), 16 words/row.
// B side XOR-swizzled by (row&14) for conflict reduction.
// Expert routing: blockIdx.z selects weight slab + row block; optional
// row gather on A and row scatter on C via g_sidx.
// ---------------------------------------------------------------------------
__global__ __launch_bounds__(256, 1)
void mma_gemm_kernel(const float* __restrict__ A, const float* __restrict__ B,
                     float* __restrict__ C, int K, int Nc, int ldB, int transB,
                     int rowsPerE, size_t wStride, int gatherF, int scatterF,
                     const float* __restrict__ bias,
                     const float* __restrict__ resid)
{
    __shared__ __align__(16) unsigned AsH[128 * 16];
    __shared__ __align__(16) unsigned AsL[128 * 16];
    __shared__ __align__(16) unsigned BsH[128 * 16];
    __shared__ __align__(16) unsigned BsL[128 * 16];

    const int t    = threadIdx.x;
    const int lane = t & 31;
    const int wid  = t >> 5;
    const int wm   = wid >> 2;          // 0..1
    const int wn   = wid & 3;           // 0..3
    const int e    = blockIdx.z;
    const int row0 = e * rowsPerE + blockIdx.y * 128;
    const int n0   = blockIdx.x * 128;
    const float* Bp = B + (size_t)e * wStride;

    // --- per-thread gmem source pointers -----------------------------------
    const float* aptr[4];
    int ar_[4], aq_[4];
    #pragma unroll
    for (int i = 0; i < 4; ++i) {
        int fid = t + 256 * i;
        int r = fid >> 3, q = fid & 7;
        ar_[i] = r; aq_[i] = q;
        int grow = row0 + r;
        int arow = gatherF ? g_sidx[grow] : grow;
        aptr[i] = A + (size_t)arow * K + q * 4;
    }

    float regA[16];
    float regB[16];
    const int KT = K / 32;

    // stage-load lambdas (inlined manually)
    // B NT mapping: i<4 -> row fid>>3, quad fid&7   (float4 along k)
    // B NN mapping: i<8 -> n = fid&127, k2 = fid>>7 (scalars along k rows)

    // ---- prologue: tile 0 -------------------------------------------------
    #pragma unroll
    for (int i = 0; i < 4; ++i)
        *(float4*)(regA + 4 * i) = *(const float4*)(aptr[i]);
    if (transB) {
        #pragma unroll
        for (int i = 0; i < 4; ++i) {
            int fid = t + 256 * i;
            *(float4*)(regB + 4 * i) =
                *(const float4*)(Bp + (size_t)(n0 + (fid >> 3)) * ldB + (fid & 7) * 4);
        }
    } else {
        #pragma unroll
        for (int i = 0; i < 8; ++i) {
            int fid = t + 256 * i;
            int n = fid & 127, k2 = fid >> 7;
            const float* s = Bp + (size_t)(2 * k2) * ldB + n0 + n;
            regB[2 * i]     = s[0];
            regB[2 * i + 1] = s[ldB];
        }
    }

    float acc[4][4][4];
    #pragma unroll
    for (int ms = 0; ms < 4; ++ms)
        #pragma unroll
        for (int ns = 0; ns < 4; ++ns)
            #pragma unroll
            for (int c = 0; c < 4; ++c) acc[ms][ns][c] = 0.f;

    for (int kt = 0; kt < KT; ++kt) {
        // ---- store staged regs to smem (split hi/lo) ----------------------
        #pragma unroll
        for (int i = 0; i < 4; ++i) {
            unsigned h0, l0, h1, l1;
            split_pack(regA[4*i],   regA[4*i+1], h0, l0);
            split_pack(regA[4*i+2], regA[4*i+3], h1, l1);
            int idx = ar_[i] * 16 + 2 * aq_[i];
            *(uint2*)&AsH[idx] = make_uint2(h0, h1);
            *(uint2*)&AsL[idx] = make_uint2(l0, l1);
        }
        if (transB) {
            #pragma unroll
            for (int i = 0; i < 4; ++i) {
                int fid = t + 256 * i;
                int r = fid >> 3, q = fid & 7;
                unsigned h0, l0, h1, l1;
                split_pack(regB[4*i],   regB[4*i+1], h0, l0);
                split_pack(regB[4*i+2], regB[4*i+3], h1, l1);
                int idx = r * 16 + ((2 * q) ^ (r & 14));
                *(uint2*)&BsH[idx] = make_uint2(h0, h1);
                *(uint2*)&BsL[idx] = make_uint2(l0, l1);
            }
        } else {
            #pragma unroll
            for (int i = 0; i < 8; ++i) {
                int fid = t + 256 * i;
                int n = fid & 127, k2 = fid >> 7;
                unsigned h, l;
                split_pack(regB[2*i], regB[2*i+1], h, l);
                int idx = n * 16 + (k2 ^ (n & 14));
                BsH[idx] = h;
                BsL[idx] = l;
            }
        }
        __syncthreads();

        // ---- prefetch next tile into regs ---------------------------------
        if (kt + 1 < KT) {
            int ko = (kt + 1) * 32;
            #pragma unroll
            for (int i = 0; i < 4; ++i)
                *(float4*)(regA + 4 * i) = *(const float4*)(aptr[i] + ko);
            if (transB) {
                #pragma unroll
                for (int i = 0; i < 4; ++i) {
                    int fid = t + 256 * i;
                    *(float4*)(regB + 4 * i) = *(const float4*)
                        (Bp + (size_t)(n0 + (fid >> 3)) * ldB + (fid & 7) * 4 + ko);
                }
            } else {
                #pragma unroll
                for (int i = 0; i < 8; ++i) {
                    int fid = t + 256 * i;
                    int n = fid & 127, k2 = fid >> 7;
                    const float* s = Bp + (size_t)(ko + 2 * k2) * ldB + n0 + n;
                    regB[2 * i]     = s[0];
                    regB[2 * i + 1] = s[ldB];
                }
            }
        }

        // ---- compute: 2 k-chunks x (Ah*Bh + Ah*Bl + Al*Bh) ----------------
        #pragma unroll
        for (int c = 0; c < 2; ++c) {
            uint2 bh[4], bl[4];
            #pragma unroll
            for (int ns = 0; ns < 4; ++ns) {
                int n = wn * 32 + ns * 8 + (lane >> 2);
                int w = (c * 8 + 2 * (lane & 3)) ^ (n & 14);
                bh[ns] = *(const uint2*)&BsH[n * 16 + w];
                bl[ns] = *(const uint2*)&BsL[n * 16 + w];
            }
            #pragma unroll
            for (int ms = 0; ms < 4; ++ms) {
                int row = wm * 64 + ms * 16 + (lane >> 2);
                int wA  = c * 8 + 2 * (lane & 3);
                uint2 ah02 = *(const uint2*)&AsH[row * 16 + wA];
                uint2 ah13 = *(const uint2*)&AsH[(row + 8) * 16 + wA];
                uint2 al02 = *(const uint2*)&AsL[row * 16 + wA];
                uint2 al13 = *(const uint2*)&AsL[(row + 8) * 16 + wA];
                #pragma unroll
                for (int ns = 0; ns < 4; ++ns) {
                    MMA_BF16(acc[ms][ns], ah02.x, ah13.x, ah02.y, ah13.y,
                             bh[ns].x, bh[ns].y);
                    MMA_BF16(acc[ms][ns], ah02.x, ah13.x, ah02.y, ah13.y,
                             bl[ns].x, bl[ns].y);
                    MMA_BF16(acc[ms][ns], al02.x, al13.x, al02.y, al13.y,
                             bh[ns].x, bh[ns].y);
                }
            }
        }
        __syncthreads();
    }

    // ---- epilogue ---------------------------------------------------------
    #pragma unroll
    for (int ms = 0; ms < 4; ++ms) {
        int r0 = row0 + wm * 64 + ms * 16 + (lane >> 2);
        int r1 = r0 + 8;
        int o0 = scatterF ? g_sidx[r0] : r0;
        int o1 = scatterF ? g_sidx[r1] : r1;
        #pragma unroll
        for (int ns = 0; ns < 4; ++ns) {
            int col = n0 + wn * 32 + ns * 8 + 2 * (lane & 3);
            float b0 = 0.f, b1 = 0.f;
            if (bias) {
                b0 = fminf(fmaxf(bias[col],     0.f), 2.f);
                b1 = fminf(fmaxf(bias[col + 1], 0.f), 2.f);
            }
            float v0 = acc[ms][ns][0] + b0, v1 = acc[ms][ns][1] + b1;
            float v2 = acc[ms][ns][2] + b0, v3 = acc[ms][ns][3] + b1;
            if (resid) {
                const float* rr0 = resid + (size_t)o0 * Nc + col;
                const float* rr1 = resid + (size_t)o1 * Nc + col;
                v0 += rr0[0]; v1 += rr0[1];
                v2 += rr1[0]; v3 += rr1[1];
            }
            *(float2*)&C[(size_t)o0 * Nc + col] = make_float2(v0, v1);
            *(float2*)&C[(size_t)o1 * Nc + col] = make_float2(v2, v3);
        }
    }
}

// ---------------------------------------------------------------------------
// Fused per-(token,head) RMSNorm + RoPE
// ---------------------------------------------------------------------------
__global__ void qknorm_rope_kernel(float* __restrict__ x,
                                   const float* __restrict__ w, int nheads)
{
    int n = blockIdx.x / nheads;
    int h = blockIdx.x % nheads;
    int d = threadIdx.x;
    float* xr = x + ((size_t)n * nheads + h) * HD_;
    float v = xr[d];
    float ss = v * v;
    #pragma unroll
    for (int o = 16; o > 0; o >>= 1) ss += __shfl_xor_sync(0xffffffffu, ss, o);
    __shared__ float ws[4];
    if ((d & 31) == 0) ws[d >> 5] = ss;
    __syncthreads();
    float tot = ws[0] + ws[1] + ws[2] + ws[3];
    float rs = rsqrtf(tot / (float)HD_ + REPS);
    __shared__ float s[HD_];
    s[d] = v * rs * w[d];
    __syncthreads();
    float pos = (float)g_pos[n];
    int fi = d & 63;
    float invf = 1.0f / (float)pow(10000.0, (double)fi / 64.0);
    float ang = pos * invf;
    float c, sn;
    sincosf(ang, &sn, &c);
    float o = (d < 64) ? (s[d] * c - s[d + 64] * sn)
                       : (s[d] * c + s[d - 64] * sn);
    xr[d] = o;
}

// ---------------------------------------------------------------------------
// Causal GQA flash attention, fp32 (unchanged from R1 — next-round target)
// ---------------------------------------------------------------------------
constexpr int ATTN_SMEM = (3 * 64 * 128 + 64 * 68 + 3 * 64) * 4;

__global__ __launch_bounds__(128)
void attn_kernel()
{
    extern __shared__ float sm[];
    float* Qs  = sm;
    float* Ks  = Qs + 64 * 128;
    float* Vs  = Ks + 64 * 128;
    float* S   = Vs + 64 * 128;
    float* m_s = S + 64 * 68;
    float* l_s = m_s + 64;
    float* al_s = l_s + 64;

    const int t    = threadIdx.x;
    const int qt   = blockIdx.x;
    const int head = blockIdx.y;
    const int kvh  = head >> 2;
    const int q0   = qt * 64;
    const float scale = 0.08838834764831845f;

    #pragma unroll
    for (int it = 0; it < 16; ++it) {
        int fid = t + it * 128;
        int r = fid >> 5, cq = fid & 31;
        *(float4*)&Qs[r*128 + cq*4] =
            *(const float4*)(g_q + (size_t)(q0 + r) * (NH_*HD_) + head * HD_ + cq * 4);
    }
    if (t < 64) { m_s[t] = -1e30f; l_s[t] = 0.f; }

    float acc[4][16];
    #pragma unroll
    for (int i = 0; i < 4; ++i)
        #pragma unroll
        for (int c = 0; c < 16; ++c) acc[i][c] = 0.f;

    const int rg = t >> 3, cg = t & 7;

    for (int kt = 0; kt <= qt; ++kt) {
        const int k0 = kt * 64;
        __syncthreads();
        #pragma unroll
        for (int it = 0; it < 16; ++it) {
            int fid = t + it * 128;
            int r = fid >> 5, cq = fid & 31;
            *(float4*)&Ks[r*128 + cq*4] =
                *(const float4*)(g_k + (size_t)(k0 + r) * (NKV_*HD_) + kvh * HD_ + cq * 4);
            *(float4*)&Vs[r*128 + cq*4] =
                *(const float4*)(g_v + (size_t)(k0 + r) * (NKV_*HD_) + kvh * HD_ + cq * 4);
        }
        __syncthreads();

        float s[4][8];
        #pragma unroll
        for (int i = 0; i < 4; ++i)
            #pragma unroll
            for (int j = 0; j < 8; ++j) s[i][j] = 0.f;
        #pragma unroll 4
        for (int d = 0; d < 128; ++d) {
            float a0 = Qs[(rg*4 + 0)*128 + d];
            float a1 = Qs[(rg*4 + 1)*128 + d];
            float a2 = Qs[(rg*4 + 2)*128 + d];
            float a3 = Qs[(rg*4 + 3)*128 + d];
            #pragma unroll
            for (int j = 0; j < 8; ++j) {
                float b = Ks[(cg*8 + j)*128 + d];
                s[0][j] = fmaf(a0, b, s[0][j]);
                s[1][j] = fmaf(a1, b, s[1][j]);
                s[2][j] = fmaf(a2, b, s[2][j]);
                s[3][j] = fmaf(a3, b, s[3][j]);
            }
        }
        const bool diag = (kt == qt);
        #pragma unroll
        for (int i = 0; i < 4; ++i) {
            int qr = q0 + rg*4 + i;
            #pragma unroll
            for (int j = 0; j < 8; ++j) {
                int kc = k0 + cg*8 + j;
                float v = s[i][j] * scale;
                if (diag && kc > qr) v = -1e9f;
                S[(rg*4 + i)*68 + cg*8 + j] = v;
            }
        }
        __syncthreads();

        if (t < 64) {
            float mold = m_s[t];
            float mx = mold;
            #pragma unroll 8
            for (int j = 0; j < 64; ++j) mx = fmaxf(mx, S[t*68 + j]);
            float sum = 0.f;
            #pragma unroll 8
            for (int j = 0; j < 64; ++j) {
                float p = __expf(S[t*68 + j] - mx);
                S[t*68 + j] = p;
                sum += p;
            }
            float al = __expf(mold - mx);
            m_s[t] = mx;
            l_s[t] = l_s[t] * al + sum;
            al_s[t] = al;
        }
        __syncthreads();

        #pragma unroll
        for (int i = 0; i < 4; ++i) {
            float al = al_s[rg*4 + i];
            #pragma unroll
            for (int c = 0; c < 16; ++c) acc[i][c] *= al;
        }
        #pragma unroll 2
        for (int j = 0; j < 64; ++j) {
            float p0 = S[(rg*4 + 0)*68 + j];
            float p1 = S[(rg*4 + 1)*68 + j];
            float p2 = S[(rg*4 + 2)*68 + j];
            float p3 = S[(rg*4 + 3)*68 + j];
            float vv[16];
            *(float4*)(vv)      = *(const float4*)&Vs[j*128 + cg*16 + 0];
            *(float4*)(vv + 4)  = *(const float4*)&Vs[j*128 + cg*16 + 4];
            *(float4*)(vv + 8)  = *(const float4*)&Vs[j*128 + cg*16 + 8];
            *(float4*)(vv + 12) = *(const float4*)&Vs[j*128 + cg*16 + 12];
            #pragma unroll
            for (int c = 0; c < 16; ++c) {
                acc[0][c] = fmaf(p0, vv[c], acc[0][c]);
                acc[1][c] = fmaf(p1, vv[c], acc[1][c]);
                acc[2][c] = fmaf(p2, vv[c], acc[2][c]);
                acc[3][c] = fmaf(p3, vv[c], acc[3][c]);
            }
        }
    }

    #pragma unroll
    for (int i = 0; i < 4; ++i) {
        int r = rg*4 + i;
        float inv = 1.f / l_s[r];
        float* op = g_attn + (size_t)(q0 + r) * (NH_*HD_) + head * HD_ + cg * 16;
        #pragma unroll
        for (int c = 0; c < 16; ++c) op[c] = acc[i][c] * inv;
    }
}

// ---------------------------------------------------------------------------
// SiLU(gate) * up
// ---------------------------------------------------------------------------
__global__ void silu_kernel()
{
    int i = blockIdx.x * 256 + threadIdx.x;
    if (i >= NTOK * EI_) return;
    int r = i / EI_, c = i % EI_;
    float gt = g_gu[(size_t)r * (2*EI_) + c];
    float up = g_gu[(size_t)r * (2*EI_) + EI_ + c];
    g_act[i] = gt / (1.f + __expf(-gt)) * up;
}

// ---------------------------------------------------------------------------
// Launcher
// ---------------------------------------------------------------------------
extern "C" void kernel_launch(void* const* d_in, const int* in_sizes, int n_in,
                              void* d_out, int out_size)
{
    const float* hidden     = (const float*)d_in[0];
    const void*  positions  = d_in[1];
    const void*  sortidx    = d_in[2];
    const float* input_ln_w = (const float*)d_in[3];
    const float* q_proj_w   = (const float*)d_in[4];
    const float* o_proj_w   = (const float*)d_in[5];
    const float* k_w        = (const float*)d_in[6];
    const float* v_w        = (const float*)d_in[7];
    const float* q_norm_w   = (const float*)d_in[8];
    const float* k_norm_w   = (const float*)d_in[9];
    const float* mu         = (const float*)d_in[10];
    const float* mu_proj_w  = (const float*)d_in[11];
    const float* post_ln_w  = (const float*)d_in[12];
    const float* gate_up_w  = (const float*)d_in[13];
    const float* down_w     = (const float*)d_in[14];

    float* out_h  = (float*)d_out;
    float* out_mu = out_h + (size_t)NTOK * DM;

    float *p_hnorm, *p_q, *p_k, *p_v, *p_attn, *p_h1, *p_hn2, *p_gu, *p_act;
    cudaGetSymbolAddress((void**)&p_hnorm, g_hnorm);
    cudaGetSymbolAddress((void**)&p_q,     g_q);
    cudaGetSymbolAddress((void**)&p_k,     g_k);
    cudaGetSymbolAddress((void**)&p_v,     g_v);
    cudaGetSymbolAddress((void**)&p_attn,  g_attn);
    cudaGetSymbolAddress((void**)&p_h1,    g_h1);
    cudaGetSymbolAddress((void**)&p_hn2,   g_hn2);
    cudaGetSymbolAddress((void**)&p_gu,    g_gu);
    cudaGetSymbolAddress((void**)&p_act,   g_act);

    cudaFuncSetAttribute(attn_kernel,
                         cudaFuncAttributeMaxDynamicSharedMemorySize, ATTN_SMEM);

    // 1) indices
    prep_idx_kernel<<<(NTOK + 255) / 256, 256>>>(positions, sortidx);

    // 2) input RMSNorm
    rmsnorm_kernel<<<NTOK, 256>>>(hidden, input_ln_w, p_hnorm);

    // 3) q = routed_proj(hnorm, q_proj_w)   NN, gather+scatter
    mma_gemm_kernel<<<dim3(16, 4, 4), 256>>>(p_hnorm, q_proj_w, p_q,
        DM, DM, DM, 0, CHK, (size_t)DM * DM, 1, 1, nullptr, nullptr);

    // 4) k = hnorm @ k_w^T ; v = hnorm @ v_w^T   NT
    mma_gemm_kernel<<<dim3(4, 16, 1), 256>>>(p_hnorm, k_w, p_k,
        DM, NKV_*HD_, DM, 1, NTOK, 0, 0, 0, nullptr, nullptr);
    mma_gemm_kernel<<<dim3(4, 16, 1), 256>>>(p_hnorm, v_w, p_v,
        DM, NKV_*HD_, DM, 1, NTOK, 0, 0, 0, nullptr, nullptr);

    // 5) per-head RMSNorm + RoPE
    qknorm_rope_kernel<<<NTOK * NH_,  HD_>>>(p_q, q_norm_w, NH_);
    qknorm_rope_kernel<<<NTOK * NKV_, HD_>>>(p_k, k_norm_w, NKV_);

    // 6) attention
    attn_kernel<<<dim3(NTOK / 64, NH_), 128, ATTN_SMEM>>>();

    // 7) h1 = hidden + routed_proj(attn, o_proj_w)   NN, gather+scatter+resid
    mma_gemm_kernel<<<dim3(16, 4, 4), 256>>>(p_attn, o_proj_w, p_h1,
        DM, DM, DM, 0, CHK, (size_t)DM * DM, 1, 1, nullptr, hidden);

    // 8) mu_current = clip(mu,0,2) + h1 @ mu_proj^T   NT + bias
    mma_gemm_kernel<<<dim3(16, 16, 1), 256>>>(p_h1, mu_proj_w, out_mu,
        DM, DM, DM, 1, NTOK, 0, 0, 0, mu, nullptr);

    // 9) post RMSNorm
    rmsnorm_kernel<<<NTOK, 256>>>(p_h1, post_ln_w, p_hn2);

    // 10) gate_up (sorted out)   NN, gather
    mma_gemm_kernel<<<dim3(32, 4, 4), 256>>>(p_hn2, gate_up_w, p_gu,
        DM, 2*EI_, 2*EI_, 0, CHK, (size_t)DM * 2 * EI_, 1, 0, nullptr, nullptr);

    // 11) act = silu(gate) * up
    silu_kernel<<<(NTOK*EI_ + 255) / 256, 256>>>();

    // 12) out_h = h1 + scatter(act @ down)   NN, scatter+resid
    mma_gemm_kernel<<<dim3(16, 4, 4), 256>>>(p_act, down_w, out_h,
        EI_, DM, DM, 0, CHK, (size_t)EI_ * DM, 0, 1, nullptr, p_h1);
}

// round 3
// speedup vs baseline: 2.6208x; 2.1079x over previous
#include <cuda_runtime.h>
#include <cuda_bf16.h>
#include <math.h>

// ---------------------------------------------------------------------------
// Problem constants
// ---------------------------------------------------------------------------
constexpr int NTOK = 2048;
constexpr int DM   = 2048;
constexpr int NH_  = 16;
constexpr int NKV_ = 4;
constexpr int HD_  = 128;
constexpr int EI_  = 2048;
constexpr int CHK  = NTOK / 4;
constexpr float REPS = 1e-6f;

// ---------------------------------------------------------------------------
// Scratch
// ---------------------------------------------------------------------------
__device__ float g_hnorm[(size_t)NTOK * DM];
__device__ float g_q   [(size_t)NTOK * DM];
__device__ float g_k   [(size_t)NTOK * NKV_ * HD_];
__device__ float g_v   [(size_t)NTOK * NKV_ * HD_];
__device__ float g_attn[(size_t)NTOK * DM];
__device__ float g_h1  [(size_t)NTOK * DM];
__device__ float g_hn2 [(size_t)NTOK * DM];
__device__ float g_gu  [(size_t)NTOK * 2 * EI_];
__device__ float g_act [(size_t)NTOK * EI_];
__device__ int   g_pos [NTOK];
__device__ int   g_sidx[NTOK];

// ---------------------------------------------------------------------------
// Index prep
// ---------------------------------------------------------------------------
__global__ void prep_idx_kernel(const void* pos, const void* sidx)
{
    int i = blockIdx.x * blockDim.x + threadIdx.x;
    if (i >= NTOK) return;
    const int* w = (const int*)pos;
    bool is64 = (w[1] == 0 && w[2] == 1);
    if (is64) {
        g_pos[i]  = (int)((const long long*)pos)[i];
        g_sidx[i] = (int)((const long long*)sidx)[i];
    } else {
        g_pos[i]  = w[i];
        g_sidx[i] = ((const int*)sidx)[i];
    }
}

// ---------------------------------------------------------------------------
// Row RMSNorm
// ---------------------------------------------------------------------------
__global__ void rmsnorm_kernel(const float* __restrict__ x,
                               const float* __restrict__ w,
                               float* __restrict__ out)
{
    int row = blockIdx.x;
    const float* xr = x + (size_t)row * DM;
    float ss = 0.f;
    for (int j = threadIdx.x; j < DM; j += 256) { float v = xr[j]; ss += v * v; }
    #pragma unroll
    for (int o = 16; o > 0; o >>= 1) ss += __shfl_xor_sync(0xffffffffu, ss, o);
    __shared__ float wsum[8];
    if ((threadIdx.x & 31) == 0) wsum[threadIdx.x >> 5] = ss;
    __syncthreads();
    float tot = 0.f;
    #pragma unroll
    for (int i = 0; i < 8; ++i) tot += wsum[i];
    float rs = rsqrtf(tot / (float)DM + REPS);
    float* orow = out + (size_t)row * DM;
    for (int j = threadIdx.x; j < DM; j += 256) orow[j] = xr[j] * rs * w[j];
}

// ---------------------------------------------------------------------------
// Split-bf16 helpers
// ---------------------------------------------------------------------------
__device__ __forceinline__ unsigned pack_bf(float x, float y)
{
    unsigned short ux = __bfloat16_as_ushort(__float2bfloat16_rn(x));
    unsigned short uy = __bfloat16_as_ushort(__float2bfloat16_rn(y));
    return (unsigned)ux | ((unsigned)uy << 16);
}
__device__ __forceinline__ void split_pack(float x, float y,
                                           unsigned& hi, unsigned& lo)
{
    __nv_bfloat16 bx = __float2bfloat16_rn(x);
    __nv_bfloat16 by = __float2bfloat16_rn(y);
    hi = (unsigned)__bfloat16_as_ushort(bx) |
         ((unsigned)__bfloat16_as_ushort(by) << 16);
    lo = pack_bf(x - __bfloat162float(bx), y - __bfloat162float(by));
}

#define MMA_BF16(d, a0, a1, a2, a3, b0, b1)                                   \
    asm volatile("mma.sync.aligned.m16n8k16.row.col.f32.bf16.bf16.f32 "       \
                 "{%0,%1,%2,%3}, {%4,%5,%6,%7}, {%8,%9}, {%0,%1,%2,%3};"      \
                 : "+f"(d[0]), "+f"(d[1]), "+f"(d[2]), "+f"(d[3])             \
                 : "r"(a0), "r"(a1), "r"(a2), "r"(a3), "r"(b0), "r"(b1))

// ---------------------------------------------------------------------------
// Tensor-core GEMM (same as R2, plus kvDual: blockIdx.z picks (B,C)/(B2,C2))
// ---------------------------------------------------------------------------
__global__ __launch_bounds__(256, 1)
void mma_gemm_kernel(const float* __restrict__ A, const float* __restrict__ B,
                     float* __restrict__ C, int K, int Nc, int ldB, int transB,
                     int rowsPerE, size_t wStride, int gatherF, int scatterF,
                     const float* __restrict__ B2, float* __restrict__ C2,
                     int kvDual,
                     const float* __restrict__ bias,
                     const float* __restrict__ resid)
{
    __shared__ __align__(16) unsigned AsH[128 * 16];
    __shared__ __align__(16) unsigned AsL[128 * 16];
    __shared__ __align__(16) unsigned BsH[128 * 16];
    __shared__ __align__(16) unsigned BsL[128 * 16];

    const int t    = threadIdx.x;
    const int lane = t & 31;
    const int wid  = t >> 5;
    const int wm   = wid >> 2;
    const int wn   = wid & 3;
    const int e    = kvDual ? 0 : blockIdx.z;
    const int row0 = e * rowsPerE + blockIdx.y * 128;
    const int n0   = blockIdx.x * 128;
    const float* Bp = (kvDual && blockIdx.z) ? B2 : B;
    Bp += (size_t)e * wStride;
    float* Cp = (kvDual && blockIdx.z) ? C2 : C;

    const float* aptr[4];
    int ar_[4], aq_[4];
    #pragma unroll
    for (int i = 0; i < 4; ++i) {
        int fid = t + 256 * i;
        int r = fid >> 3, q = fid & 7;
        ar_[i] = r; aq_[i] = q;
        int grow = row0 + r;
        int arow = gatherF ? g_sidx[grow] : grow;
        aptr[i] = A + (size_t)arow * K + q * 4;
    }

    float regA[16];
    float regB[16];
    const int KT = K / 32;

    #pragma unroll
    for (int i = 0; i < 4; ++i)
        *(float4*)(regA + 4 * i) = *(const float4*)(aptr[i]);
    if (transB) {
        #pragma unroll
        for (int i = 0; i < 4; ++i) {
            int fid = t + 256 * i;
            *(float4*)(regB + 4 * i) =
                *(const float4*)(Bp + (size_t)(n0 + (fid >> 3)) * ldB + (fid & 7) * 4);
        }
    } else {
        #pragma unroll
        for (int i = 0; i < 8; ++i) {
            int fid = t + 256 * i;
            int n = fid & 127, k2 = fid >> 7;
            const float* s = Bp + (size_t)(2 * k2) * ldB + n0 + n;
            regB[2 * i]     = s[0];
            regB[2 * i + 1] = s[ldB];
        }
    }

    float acc[4][4][4];
    #pragma unroll
    for (int ms = 0; ms < 4; ++ms)
        #pragma unroll
        for (int ns = 0; ns < 4; ++ns)
            #pragma unroll
            for (int c = 0; c < 4; ++c) acc[ms][ns][c] = 0.f;

    for (int kt = 0; kt < KT; ++kt) {
        #pragma unroll
        for (int i = 0; i < 4; ++i) {
            unsigned h0, l0, h1, l1;
            split_pack(regA[4*i],   regA[4*i+1], h0, l0);
            split_pack(regA[4*i+2], regA[4*i+3], h1, l1);
            int idx = ar_[i] * 16 + 2 * aq_[i];
            *(uint2*)&AsH[idx] = make_uint2(h0, h1);
            *(uint2*)&AsL[idx] = make_uint2(l0, l1);
        }
        if (transB) {
            #pragma unroll
            for (int i = 0; i < 4; ++i) {
                int fid = t + 256 * i;
                int r = fid >> 3, q = fid & 7;
                unsigned h0, l0, h1, l1;
                split_pack(regB[4*i],   regB[4*i+1], h0, l0);
                split_pack(regB[4*i+2], regB[4*i+3], h1, l1);
                int idx = r * 16 + ((2 * q) ^ (r & 14));
                *(uint2*)&BsH[idx] = make_uint2(h0, h1);
                *(uint2*)&BsL[idx] = make_uint2(l0, l1);
            }
        } else {
            #pragma unroll
            for (int i = 0; i < 8; ++i) {
                int fid = t + 256 * i;
                int n = fid & 127, k2 = fid >> 7;
                unsigned h, l;
                split_pack(regB[2*i], regB[2*i+1], h, l);
                int idx = n * 16 + (k2 ^ (n & 14));
                BsH[idx] = h;
                BsL[idx] = l;
            }
        }
        __syncthreads();

        if (kt + 1 < KT) {
            int ko = (kt + 1) * 32;
            #pragma unroll
            for (int i = 0; i < 4; ++i)
                *(float4*)(regA + 4 * i) = *(const float4*)(aptr[i] + ko);
            if (transB) {
                #pragma unroll
                for (int i = 0; i < 4; ++i) {
                    int fid = t + 256 * i;
                    *(float4*)(regB + 4 * i) = *(const float4*)
                        (Bp + (size_t)(n0 + (fid >> 3)) * ldB + (fid & 7) * 4 + ko);
                }
            } else {
                #pragma unroll
                for (int i = 0; i < 8; ++i) {
                    int fid = t + 256 * i;
                    int n = fid & 127, k2 = fid >> 7;
                    const float* s = Bp + (size_t)(ko + 2 * k2) * ldB + n0 + n;
                    regB[2 * i]     = s[0];
                    regB[2 * i + 1] = s[ldB];
                }
            }
        }

        #pragma unroll
        for (int c = 0; c < 2; ++c) {
            uint2 bh[4], bl[4];
            #pragma unroll
            for (int ns = 0; ns < 4; ++ns) {
                int n = wn * 32 + ns * 8 + (lane >> 2);
                int w = (c * 8 + 2 * (lane & 3)) ^ (n & 14);
                bh[ns] = *(const uint2*)&BsH[n * 16 + w];
                bl[ns] = *(const uint2*)&BsL[n * 16 + w];
            }
            #pragma unroll
            for (int ms = 0; ms < 4; ++ms) {
                int row = wm * 64 + ms * 16 + (lane >> 2);
                int wA  = c * 8 + 2 * (lane & 3);
                uint2 ah02 = *(const uint2*)&AsH[row * 16 + wA];
                uint2 ah13 = *(const uint2*)&AsH[(row + 8) * 16 + wA];
                uint2 al02 = *(const uint2*)&AsL[row * 16 + wA];
                uint2 al13 = *(const uint2*)&AsL[(row + 8) * 16 + wA];
                #pragma unroll
                for (int ns = 0; ns < 4; ++ns) {
                    MMA_BF16(acc[ms][ns], ah02.x, ah13.x, ah02.y, ah13.y,
                             bh[ns].x, bh[ns].y);
                    MMA_BF16(acc[ms][ns], ah02.x, ah13.x, ah02.y, ah13.y,
                             bl[ns].x, bl[ns].y);
                    MMA_BF16(acc[ms][ns], al02.x, al13.x, al02.y, al13.y,
                             bh[ns].x, bh[ns].y);
                }
            }
        }
        __syncthreads();
    }

    #pragma unroll
    for (int ms = 0; ms < 4; ++ms) {
        int r0 = row0 + wm * 64 + ms * 16 + (lane >> 2);
        int r1 = r0 + 8;
        int o0 = scatterF ? g_sidx[r0] : r0;
        int o1 = scatterF ? g_sidx[r1] : r1;
        #pragma unroll
        for (int ns = 0; ns < 4; ++ns) {
            int col = n0 + wn * 32 + ns * 8 + 2 * (lane & 3);
            float b0 = 0.f, b1 = 0.f;
            if (bias) {
                b0 = fminf(fmaxf(bias[col],     0.f), 2.f);
                b1 = fminf(fmaxf(bias[col + 1], 0.f), 2.f);
            }
            float v0 = acc[ms][ns][0] + b0, v1 = acc[ms][ns][1] + b1;
            float v2 = acc[ms][ns][2] + b0, v3 = acc[ms][ns][3] + b1;
            if (resid) {
                const float* rr0 = resid + (size_t)o0 * Nc + col;
                const float* rr1 = resid + (size_t)o1 * Nc + col;
                v0 += rr0[0]; v1 += rr0[1];
                v2 += rr1[0]; v3 += rr1[1];
            }
            *(float2*)&Cp[(size_t)o0 * Nc + col] = make_float2(v0, v1);
            *(float2*)&Cp[(size_t)o1 * Nc + col] = make_float2(v2, v3);
        }
    }
}

// ---------------------------------------------------------------------------
// Fused per-(token,head) RMSNorm + RoPE (FP32 exp2f, no double pow)
// ---------------------------------------------------------------------------
__global__ void qknorm_rope_kernel(float* __restrict__ x,
                                   const float* __restrict__ w, int nheads)
{
    int n = blockIdx.x / nheads;
    int h = blockIdx.x % nheads;
    int d = threadIdx.x;
    float* xr = x + ((size_t)n * nheads + h) * HD_;
    float v = xr[d];
    float ss = v * v;
    #pragma unroll
    for (int o = 16; o > 0; o >>= 1) ss += __shfl_xor_sync(0xffffffffu, ss, o);
    __shared__ float ws[4];
    if ((d & 31) == 0) ws[d >> 5] = ss;
    __syncthreads();
    float tot = ws[0] + ws[1] + ws[2] + ws[3];
    float rs = rsqrtf(tot / (float)HD_ + REPS);
    __shared__ float s[HD_];
    s[d] = v * rs * w[d];
    __syncthreads();
    float pos = (float)g_pos[n];
    int fi = d & 63;
    // 1/theta^(fi/64) = exp2(-fi * log2(10000)/64)
    float invf = exp2f(-(float)fi * 0.2076205059304602f);
    float ang = pos * invf;
    float c, sn;
    sincosf(ang, &sn, &c);
    float o = (d < 64) ? (s[d] * c - s[d + 64] * sn)
                       : (s[d] * c + s[d - 64] * sn);
    xr[d] = o;
}

// ---------------------------------------------------------------------------
// Tensor-core causal GQA flash attention (split-bf16, 3-term).
// CTA = (head, 128 q rows), 256 threads = 8 warps (16 q rows each).
// KV tiles of 64. Q held in registers as pre-split fragments.
// ---------------------------------------------------------------------------
constexpr int ATT_SMEM_WORDS =
    64*72*2 +      // KsH/KsL
    128*40*2 +     // VsH/VsL
    128*66 +       // Ss (fp32)
    128*40*2 +     // PsH/PsL
    3*128;         // m, l, alpha
constexpr int ATT_SMEM = ATT_SMEM_WORDS * 4;

__global__ __launch_bounds__(256, 1)
void attn_mma_kernel()
{
    extern __shared__ unsigned smu[];
    unsigned* KsH = smu;
    unsigned* KsL = KsH + 64*72;
    unsigned* VsH = KsL + 64*72;
    unsigned* VsL = VsH + 128*40;
    float*    Ss  = (float*)(VsL + 128*40);
    unsigned* PsH = (unsigned*)(Ss + 128*66);
    unsigned* PsL = PsH + 128*40;
    float*    m_s = (float*)(PsL + 128*40);
    float*    l_s = m_s + 128;
    float*    al_s = l_s + 128;

    const int t    = threadIdx.x;
    const int lane = t & 31;
    const int wid  = t >> 5;
    const int g    = lane >> 2;
    const int tq   = lane & 3;
    const int qt   = 15 - (blockIdx.x >> 4);   // heavy tiles first
    const int head = blockIdx.x & 15;
    const int kvh  = head >> 2;
    const int q0   = qt * 128;
    const float scale = 0.08838834764831845f;

    // ---- Q fragments in registers (hi/lo), 8 k16 chunks -------------------
    unsigned qh[8][4], ql[8][4];
    {
        const float* b0 = g_q + (size_t)(q0 + wid*16 + g) * (NH_*HD_) + head*HD_;
        const float* b8 = b0 + 8 * (NH_*HD_);
        #pragma unroll
        for (int c = 0; c < 8; ++c) {
            float4 v0 = *(const float4*)(b0 + c*16 + 4*tq);
            float4 v8 = *(const float4*)(b8 + c*16 + 4*tq);
            split_pack(v0.x, v0.y, qh[c][0], ql[c][0]);
            split_pack(v8.x, v8.y, qh[c][1], ql[c][1]);
            split_pack(v0.z, v0.w, qh[c][2], ql[c][2]);
            split_pack(v8.z, v8.w, qh[c][3], ql[c][3]);
        }
    }
    if (t < 128) { m_s[t] = -1e30f; l_s[t] = 0.f; }

    float oacc[16][4];
    #pragma unroll
    for (int nf = 0; nf < 16; ++nf)
        #pragma unroll
        for (int c = 0; c < 4; ++c) oacc[nf][c] = 0.f;

    const int nkv = 2*qt + 2;
    for (int kt = 0; kt < nkv; ++kt) {
        const int k0 = kt * 64;
        __syncthreads();
        // ---- stage K tile (64 x 128) ----
        #pragma unroll
        for (int i = 0; i < 8; ++i) {
            int fid = t + 256 * i;            // 2048 float4 groups
            int r = fid >> 5, q = fid & 31;
            float4 v = *(const float4*)
                (g_k + (size_t)(k0 + r) * (NKV_*HD_) + kvh*HD_ + 4*q);
            unsigned h0, l0, h1, l1;
            split_pack(v.x, v.y, h0, l0);
            split_pack(v.z, v.w, h1, l1);
            int idx = r*72 + 2*q;
            KsH[idx] = h0; KsH[idx+1] = h1;
            KsL[idx] = l0; KsL[idx+1] = l1;
        }
        // ---- stage V tile: word(n=hd, k2=key pair) ----
        #pragma unroll
        for (int i = 0; i < 16; ++i) {
            int wo = t + 256 * i;             // 4096 words
            int n = wo & 127, k2 = wo >> 7;
            const float* s = g_v + (size_t)(k0 + 2*k2) * (NKV_*HD_) + kvh*HD_ + n;
            unsigned h, l;
            split_pack(s[0], s[NKV_*HD_], h, l);
            VsH[n*40 + k2] = h;
            VsL[n*40 + k2] = l;
        }
        __syncthreads();

        // ---- S = Q K^T ----
        float sacc[8][4];
        #pragma unroll
        for (int ns = 0; ns < 8; ++ns)
            #pragma unroll
            for (int c = 0; c < 4; ++c) sacc[ns][c] = 0.f;
        #pragma unroll
        for (int c = 0; c < 8; ++c) {
            #pragma unroll
            for (int ns = 0; ns < 8; ++ns) {
                int key = ns*8 + g;
                uint2 bh = *(const uint2*)&KsH[key*72 + c*8 + 2*tq];
                uint2 bl = *(const uint2*)&KsL[key*72 + c*8 + 2*tq];
                MMA_BF16(sacc[ns], qh[c][0], qh[c][1], qh[c][2], qh[c][3],
                         bh.x, bh.y);
                MMA_BF16(sacc[ns], qh[c][0], qh[c][1], qh[c][2], qh[c][3],
                         bl.x, bl.y);
                MMA_BF16(sacc[ns], ql[c][0], ql[c][1], ql[c][2], ql[c][3],
                         bh.x, bh.y);
            }
        }
        {
            int r = wid*16 + g;
            #pragma unroll
            for (int ns = 0; ns < 8; ++ns) {
                *(float2*)&Ss[r*66 + ns*8 + 2*tq] =
                    make_float2(sacc[ns][0], sacc[ns][1]);
                *(float2*)&Ss[(r+8)*66 + ns*8 + 2*tq] =
                    make_float2(sacc[ns][2], sacc[ns][3]);
            }
        }
        __syncthreads();

        // ---- online softmax: 2 threads per row ----
        {
            int r = t >> 1, half = t & 1;
            int qrow = q0 + r;
            const float* srow = Ss + r*66 + half*32;
            int cbase = k0 + half*32;
            float mx = -1e30f;
            #pragma unroll 8
            for (int j = 0; j < 32; ++j) {
                float x = (cbase + j <= qrow) ? srow[j] * scale : -1e30f;
                mx = fmaxf(mx, x);
            }
            mx = fmaxf(mx, __shfl_xor_sync(0xffffffffu, mx, 1));
            float mold = m_s[r];
            float mnew = fmaxf(mold, mx);
            float sum = 0.f;
            #pragma unroll 4
            for (int j = 0; j < 16; ++j) {
                float x0 = (cbase + 2*j     <= qrow) ? srow[2*j]   * scale : -1e30f;
                float x1 = (cbase + 2*j + 1 <= qrow) ? srow[2*j+1] * scale : -1e30f;
                float p0 = __expf(x0 - mnew);
                float p1 = __expf(x1 - mnew);
                sum += p0 + p1;
                unsigned h, l;
                split_pack(p0, p1, h, l);
                PsH[r*40 + half*16 + j] = h;
                PsL[r*40 + half*16 + j] = l;
            }
            sum += __shfl_xor_sync(0xffffffffu, sum, 1);
            if (half == 0) {
                float al = __expf(mold - mnew);
                m_s[r] = mnew;
                l_s[r] = l_s[r] * al + sum;
                al_s[r] = al;
            }
        }
        __syncthreads();

        // ---- O = O*alpha + P V ----
        {
            float al0 = al_s[wid*16 + g];
            float al8 = al_s[wid*16 + g + 8];
            #pragma unroll
            for (int nf = 0; nf < 16; ++nf) {
                oacc[nf][0] *= al0; oacc[nf][1] *= al0;
                oacc[nf][2] *= al8; oacc[nf][3] *= al8;
            }
        }
        #pragma unroll
        for (int c = 0; c < 4; ++c) {
            int r = wid*16 + g;
            int w = c*8 + 2*tq;
            uint2 ph02 = *(const uint2*)&PsH[r*40 + w];
            uint2 ph13 = *(const uint2*)&PsH[(r+8)*40 + w];
            uint2 pl02 = *(const uint2*)&PsL[r*40 + w];
            uint2 pl13 = *(const uint2*)&PsL[(r+8)*40 + w];
            #pragma unroll
            for (int nf = 0; nf < 16; ++nf) {
                int n = nf*8 + g;
                uint2 vh = *(const uint2*)&VsH[n*40 + w];
                uint2 vl = *(const uint2*)&VsL[n*40 + w];
                MMA_BF16(oacc[nf], ph02.x, ph13.x, ph02.y, ph13.y, vh.x, vh.y);
                MMA_BF16(oacc[nf], ph02.x, ph13.x, ph02.y, ph13.y, vl.x, vl.y);
                MMA_BF16(oacc[nf], pl02.x, pl13.x, pl02.y, pl13.y, vh.x, vh.y);
            }
        }
    }

    // ---- epilogue ----
    {
        int r = wid*16 + g;
        float inv0 = 1.f / l_s[r];
        float inv8 = 1.f / l_s[r + 8];
        float* o0 = g_attn + (size_t)(q0 + r) * (NH_*HD_) + head*HD_;
        float* o8 = o0 + 8 * (NH_*HD_);
        #pragma unroll
        for (int nf = 0; nf < 16; ++nf) {
            int col = nf*8 + 2*tq;
            *(float2*)&o0[col] = make_float2(oacc[nf][0]*inv0, oacc[nf][1]*inv0);
            *(float2*)&o8[col] = make_float2(oacc[nf][2]*inv8, oacc[nf][3]*inv8);
        }
    }
}

// ---------------------------------------------------------------------------
// SiLU(gate) * up
// ---------------------------------------------------------------------------
__global__ void silu_kernel()
{
    int i = blockIdx.x * 256 + threadIdx.x;
    if (i >= NTOK * EI_) return;
    int r = i / EI_, c = i % EI_;
    float gt = g_gu[(size_t)r * (2*EI_) + c];
    float up = g_gu[(size_t)r * (2*EI_) + EI_ + c];
    g_act[i] = gt / (1.f + __expf(-gt)) * up;
}

// ---------------------------------------------------------------------------
// Launcher
// ---------------------------------------------------------------------------
extern "C" void kernel_launch(void* const* d_in, const int* in_sizes, int n_in,
                              void* d_out, int out_size)
{
    const float* hidden     = (const float*)d_in[0];
    const void*  positions  = d_in[1];
    const void*  sortidx    = d_in[2];
    const float* input_ln_w = (const float*)d_in[3];
    const float* q_proj_w   = (const float*)d_in[4];
    const float* o_proj_w   = (const float*)d_in[5];
    const float* k_w        = (const float*)d_in[6];
    const float* v_w        = (const float*)d_in[7];
    const float* q_norm_w   = (const float*)d_in[8];
    const float* k_norm_w   = (const float*)d_in[9];
    const float* mu         = (const float*)d_in[10];
    const float* mu_proj_w  = (const float*)d_in[11];
    const float* post_ln_w  = (const float*)d_in[12];
    const float* gate_up_w  = (const float*)d_in[13];
    const float* down_w     = (const float*)d_in[14];

    float* out_h  = (float*)d_out;
    float* out_mu = out_h + (size_t)NTOK * DM;

    float *p_hnorm, *p_q, *p_k, *p_v, *p_attn, *p_h1, *p_hn2, *p_gu, *p_act;
    cudaGetSymbolAddress((void**)&p_hnorm, g_hnorm);
    cudaGetSymbolAddress((void**)&p_q,     g_q);
    cudaGetSymbolAddress((void**)&p_k,     g_k);
    cudaGetSymbolAddress((void**)&p_v,     g_v);
    cudaGetSymbolAddress((void**)&p_attn,  g_attn);
    cudaGetSymbolAddress((void**)&p_h1,    g_h1);
    cudaGetSymbolAddress((void**)&p_hn2,   g_hn2);
    cudaGetSymbolAddress((void**)&p_gu,    g_gu);
    cudaGetSymbolAddress((void**)&p_act,   g_act);

    cudaFuncSetAttribute(attn_mma_kernel,
                         cudaFuncAttributeMaxDynamicSharedMemorySize, ATT_SMEM);

    // 1) indices
    prep_idx_kernel<<<(NTOK + 255) / 256, 256>>>(positions, sortidx);

    // 2) input RMSNorm
    rmsnorm_kernel<<<NTOK, 256>>>(hidden, input_ln_w, p_hnorm);

    // 3) q = routed_proj(hnorm, q_proj_w)  NN gather+scatter
    mma_gemm_kernel<<<dim3(16, 4, 4), 256>>>(p_hnorm, q_proj_w, p_q,
        DM, DM, DM, 0, CHK, (size_t)DM * DM, 1, 1,
        nullptr, nullptr, 0, nullptr, nullptr);

    // 4) k,v = hnorm @ {k_w,v_w}^T   NT, fused via blockIdx.z
    mma_gemm_kernel<<<dim3(4, 16, 2), 256>>>(p_hnorm, k_w, p_k,
        DM, NKV_*HD_, DM, 1, NTOK, 0, 0, 0,
        v_w, p_v, 1, nullptr, nullptr);

    // 5) per-head RMSNorm + RoPE
    qknorm_rope_kernel<<<NTOK * NH_,  HD_>>>(p_q, q_norm_w, NH_);
    qknorm_rope_kernel<<<NTOK * NKV_, HD_>>>(p_k, k_norm_w, NKV_);

    // 6) attention (tensor-core)
    attn_mma_kernel<<<256, 256, ATT_SMEM>>>();

    // 7) h1 = hidden + routed_proj(attn, o_proj_w)
    mma_gemm_kernel<<<dim3(16, 4, 4), 256>>>(p_attn, o_proj_w, p_h1,
        DM, DM, DM, 0, CHK, (size_t)DM * DM, 1, 1,
        nullptr, nullptr, 0, nullptr, hidden);

    // 8) mu_current = clip(mu,0,2) + h1 @ mu_proj^T
    mma_gemm_kernel<<<dim3(16, 16, 1), 256>>>(p_h1, mu_proj_w, out_mu,
        DM, DM, DM, 1, NTOK, 0, 0, 0,
        nullptr, nullptr, 0, mu, nullptr);

    // 9) post RMSNorm
    rmsnorm_kernel<<<NTOK, 256>>>(p_h1, post_ln_w, p_hn2);

    // 10) gate_up  NN gather
    mma_gemm_kernel<<<dim3(32, 4, 4), 256>>>(p_hn2, gate_up_w, p_gu,
        DM, 2*EI_, 2*EI_, 0, CHK, (size_t)DM * 2 * EI_, 1, 0,
        nullptr, nullptr, 0, nullptr, nullptr);

    // 11) act = silu(gate) * up
    silu_kernel<<<(NTOK*EI_ + 255) / 256, 256>>>();

    // 12) out_h = h1 + scatter(act @ down)
    mma_gemm_kernel<<<dim3(16, 4, 4), 256>>>(p_act, down_w, out_h,
        EI_, DM, DM, 0, CHK, (size_t)EI_ * DM, 0, 1,
        nullptr, nullptr, 0, nullptr, p_h1);
}